// round 3
// baseline (speedup 1.0000x reference)
#include <cuda_runtime.h>

#define B_CHAIN 16384
#define S_SIDE 15
#define NATM (1 + B_CHAIN + B_CHAIN * S_SIDE)

#define NB 128   // kernel A blocks
#define NT 128   // kernel A threads per block (NB*NT == B_CHAIN)

// Scratch (device globals; g_flag is zero-initialized at module load and
// reset by kernel B each run so every replay starts clean)
__device__ float g_global[12 * B_CHAIN];   // backbone global transforms (SoA)
__device__ float g_agg[NB * 12];           // block aggregates (AoS)
__device__ int   g_flag[NB];               // publish flags

struct Aff { float m[12]; };  // row-major 3x4 affine; m[r*4+3] = translation

__device__ __forceinline__ Aff aff_identity() {
    Aff I;
#pragma unroll
    for (int k = 0; k < 12; ++k) I.m[k] = 0.0f;
    I.m[0] = I.m[5] = I.m[10] = 1.0f;
    return I;
}

// C = A * B (affine compose, implicit bottom row [0 0 0 1])
__device__ __forceinline__ Aff aff_mul(const Aff& A, const Aff& B) {
    Aff C;
#pragma unroll
    for (int r = 0; r < 3; ++r) {
#pragma unroll
        for (int c = 0; c < 4; ++c) {
            float s = A.m[r*4+0] * B.m[0*4+c]
                    + A.m[r*4+1] * B.m[1*4+c]
                    + A.m[r*4+2] * B.m[2*4+c];
            if (c == 3) s += A.m[r*4+3];
            C.m[r*4+c] = s;
        }
    }
    return C;
}

__device__ __forceinline__ Aff shfl_up_aff(const Aff& a, int delta, int width) {
    Aff r;
#pragma unroll
    for (int k = 0; k < 12; ++k)
        r.m[k] = __shfl_up_sync(0xffffffffu, a.m[k], delta, width);
    return r;
}

__device__ __forceinline__ Aff shfl_down_aff(const Aff& a, int delta) {
    Aff r;
#pragma unroll
    for (int k = 0; k < 12; ++k)
        r.m[k] = __shfl_down_sync(0xffffffffu, a.m[k], delta, 32);
    return r;
}

// Per-node homogeneous transform (closed forms).
// doftype==2 (bond): Rx(d0) Rz(d1) T(d2,0,0) Rx(d3)
// doftype==1 (jump): T(d0,d1,d2) Rz(d5) Ry(d4) Rx(d3)
// doftype==0: identity
__device__ __forceinline__ Aff build_ht(int n,
                                        const float4* __restrict__ dofs4,
                                        const float* __restrict__ full_dofs,
                                        const int* __restrict__ doftype) {
    int dt = doftype[n];
    if (dt == 0) return aff_identity();

    float4 d = dofs4[n - 1];
    Aff H;
    if (dt == 2) {
        float sa, ca, sb, cb, sc, cc;
        sincosf(d.x, &sa, &ca);
        sincosf(d.y, &sb, &cb);
        sincosf(d.w, &sc, &cc);
        float x = d.z;
        H.m[0] = cb;      H.m[1]  = -sb * cc;             H.m[2]  = sb * sc;               H.m[3]  = cb * x;
        H.m[4] = ca * sb; H.m[5]  = ca * cb * cc - sa*sc; H.m[6]  = -ca * cb * sc - sa*cc; H.m[7]  = ca * sb * x;
        H.m[8] = sa * sb; H.m[9]  = sa * cb * cc + ca*sc; H.m[10] = -sa * cb * sc + ca*cc; H.m[11] = sa * sb * x;
    } else {
        float a = d.w;
        float b = full_dofs[n * 9 + 4];
        float g = full_dofs[n * 9 + 5];
        float sa, ca, sb, cb, sg, cg;
        sincosf(a, &sa, &ca);
        sincosf(b, &sb, &cb);
        sincosf(g, &sg, &cg);
        H.m[0] = cg * cb; H.m[1]  = cg * sb * sa - sg * ca; H.m[2]  = cg * sb * ca + sg * sa; H.m[3]  = d.x;
        H.m[4] = sg * cb; H.m[5]  = sg * sb * sa + cg * ca; H.m[6]  = sg * sb * ca - cg * sa; H.m[7]  = d.y;
        H.m[8] = -sb;     H.m[9]  = cb * sa;                H.m[10] = cb * ca;                H.m[11] = d.z;
    }
    return H;
}

// ---------------- Kernel A: fused backbone scan (single wave + lookback) -----
__global__ void __launch_bounds__(NT)
kA_backbone(const float4* __restrict__ dofs4,
            const float* __restrict__ full_dofs,
            const int* __restrict__ doftype,
            const int* __restrict__ kin_id,
            float* __restrict__ out) {
    const int t    = threadIdx.x;
    const int bid  = blockIdx.x;
    const int item = bid * NT + t;
    const int n    = item + 1;
    const int lane = t & 31;
    const int warp = t >> 5;

    Aff M = build_ht(n, dofs4, full_dofs, doftype);

    // warp-level inclusive scan (no barriers)
#pragma unroll
    for (int d = 1; d < 32; d <<= 1) {
        Aff P = shfl_up_aff(M, d, 32);
        if (lane >= d) M = aff_mul(P, M);
    }

    // cross-warp fixup
    __shared__ float wagg[4][12];
    __shared__ float wred[4][12];
    if (lane == 31) {
#pragma unroll
        for (int k = 0; k < 12; ++k) wagg[warp][k] = M.m[k];
    }
    __syncthreads();
    {
        Aff Wp = aff_identity();
        for (int w = 0; w < warp; ++w) {
            Aff A;
#pragma unroll
            for (int k = 0; k < 12; ++k) A.m[k] = wagg[w][k];
            Wp = aff_mul(Wp, A);
        }
        M = aff_mul(Wp, M);   // block-local inclusive value
    }

    // publish block aggregate (thread NT-1 holds it)
    if (t == NT - 1) {
#pragma unroll
        for (int k = 0; k < 12; ++k) g_agg[bid * 12 + k] = M.m[k];
        __threadfence();
        atomicExch(&g_flag[bid], 1);
    }

    // lookback: thread i covers predecessor block i (identity for i >= bid)
    Aff V = aff_identity();
    if (t < bid) {
        volatile int* vf = (volatile int*)g_flag;
        while (vf[t] == 0) { }
        __threadfence();
#pragma unroll
        for (int k = 0; k < 12; ++k) V.m[k] = __ldcg(&g_agg[t * 12 + k]);
    }
    // ordered tree reduce across the 128 threads (order preserved)
#pragma unroll
    for (int d = 1; d < 32; d <<= 1) {
        Aff H = shfl_down_aff(V, d);
        if ((lane & (2 * d - 1)) == 0) V = aff_mul(V, H);
    }
    if (lane == 0) {
#pragma unroll
        for (int k = 0; k < 12; ++k) wred[warp][k] = V.m[k];
    }
    __syncthreads();
    {
        Aff w0, w1, w2, w3;
#pragma unroll
        for (int k = 0; k < 12; ++k) { w0.m[k] = wred[0][k]; w1.m[k] = wred[1][k];
                                       w2.m[k] = wred[2][k]; w3.m[k] = wred[3][k]; }
        Aff E = aff_mul(aff_mul(w0, w1), aff_mul(w2, w3));  // exclusive block prefix
        M = aff_mul(E, M);                                  // global transform of node n
    }

    // backbone coordinate
    {
        int o = kin_id[n];
        out[o * 3 + 0] = M.m[3];
        out[o * 3 + 1] = M.m[7];
        out[o * 3 + 2] = M.m[11];
    }
    // stash for side-chain kernel (SoA, coalesced)
#pragma unroll
    for (int k = 0; k < 12; ++k) g_global[k * B_CHAIN + item] = M.m[k];
}

// ---------------- Kernel B: side chains, 16 lanes per chain ------------------
#define KB_THREADS 256
__global__ void __launch_bounds__(KB_THREADS)
kB_side(const float4* __restrict__ dofs4,
        const float* __restrict__ full_dofs,
        const int* __restrict__ doftype,
        const int* __restrict__ kin_id,
        float* __restrict__ out) {
    // reset flags for the next graph replay (stream-ordered after kernel A)
    if (blockIdx.x == 0 && threadIdx.x < NB) g_flag[threadIdx.x] = 0;

    const int gt    = blockIdx.x * KB_THREADS + threadIdx.x;
    const int chain = gt >> 4;       // backbone item 0..B_CHAIN-1
    const int d     = gt & 15;       // lane within chain

    Aff M;
    int ns = 0;
    if (d == 0) {
        // lane 0 carries the backbone global transform
#pragma unroll
        for (int k = 0; k < 12; ++k) M.m[k] = g_global[k * B_CHAIN + chain];
    } else {
        ns = 1 + B_CHAIN + chain * S_SIDE + (d - 1);
        M = build_ht(ns, dofs4, full_dofs, doftype);
    }

    // segmented inclusive scan over 16 lanes
#pragma unroll
    for (int dd = 1; dd < 16; dd <<= 1) {
        Aff P = shfl_up_aff(M, dd, 16);
        if (d >= dd) M = aff_mul(P, M);
    }

    if (d > 0) {
        int o = kin_id[ns];
        out[o * 3 + 0] = M.m[3];
        out[o * 3 + 1] = M.m[7];
        out[o * 3 + 2] = M.m[11];
    }
}

// ---------------- launch -----------------------------------------------------
extern "C" void kernel_launch(void* const* d_in, const int* in_sizes, int n_in,
                              void* d_out, int out_size) {
    // metadata order: dofs, full_dofs, node_idx, dof_idx, doftype,
    //                 gen0_nodes, gen1_nodes, gen1_parents, kin_id
    const float4* dofs4     = (const float4*)d_in[0];
    const float*  full_dofs = (const float*)d_in[1];
    const int*    doftype   = (const int*)d_in[4];
    const int*    kin_id    = (const int*)d_in[8];
    float* out = (float*)d_out;

    kA_backbone<<<NB, NT>>>(dofs4, full_dofs, doftype, kin_id, out);

    int kb_blocks = (B_CHAIN * 16) / KB_THREADS;  // 1024
    kB_side<<<kb_blocks, KB_THREADS>>>(dofs4, full_dofs, doftype, kin_id, out);
}

// round 5
// speedup vs baseline: 1.1898x; 1.1898x over previous
#include <cuda_runtime.h>

#define B_CHAIN 16384
#define S_SIDE 15
#define NATM (1 + B_CHAIN + B_CHAIN * S_SIDE)

#define NB 128   // blocks (single wave: NB <= 148 SMs, guaranteed co-resident)
#define NT 128   // threads per block; NB*NT == B_CHAIN

// Scratch (device globals; zero-initialized at module load; g_flag/g_done are
// reset at the end of every run by the last-finishing block, so each graph
// replay starts clean).
__device__ float g_agg[NB * 12];   // block aggregates (AoS)
__device__ int   g_flag[NB];       // publish flags
__device__ int   g_done;           // lookback completion counter

struct Aff { float m[12]; };  // row-major 3x4 affine; m[r*4+3] = translation

__device__ __forceinline__ Aff aff_identity() {
    Aff I;
#pragma unroll
    for (int k = 0; k < 12; ++k) I.m[k] = 0.0f;
    I.m[0] = I.m[5] = I.m[10] = 1.0f;
    return I;
}

// C = A * B (affine compose, implicit bottom row [0 0 0 1])
__device__ __forceinline__ Aff aff_mul(const Aff& A, const Aff& B) {
    Aff C;
#pragma unroll
    for (int r = 0; r < 3; ++r) {
#pragma unroll
        for (int c = 0; c < 4; ++c) {
            float s = A.m[r*4+0] * B.m[0*4+c]
                    + A.m[r*4+1] * B.m[1*4+c]
                    + A.m[r*4+2] * B.m[2*4+c];
            if (c == 3) s += A.m[r*4+3];
            C.m[r*4+c] = s;
        }
    }
    return C;
}

__device__ __forceinline__ Aff shfl_up_aff(const Aff& a, int delta) {
    Aff r;
#pragma unroll
    for (int k = 0; k < 12; ++k)
        r.m[k] = __shfl_up_sync(0xffffffffu, a.m[k], delta, 32);
    return r;
}

__device__ __forceinline__ Aff shfl_down_aff(const Aff& a, int delta) {
    Aff r;
#pragma unroll
    for (int k = 0; k < 12; ++k)
        r.m[k] = __shfl_down_sync(0xffffffffu, a.m[k], delta, 32);
    return r;
}

// Per-node homogeneous transform (closed forms, fast-math sincos).
// doftype==2 (bond): Rx(d0) Rz(d1) T(d2,0,0) Rx(d3)
// doftype==1 (jump): T(d0,d1,d2) Rz(d5) Ry(d4) Rx(d3)
// doftype==0: identity
__device__ __forceinline__ Aff build_ht_from(int dt, float4 d, int n,
                                             const float* __restrict__ full_dofs) {
    if (dt == 0) return aff_identity();
    Aff H;
    if (dt == 2) {
        float sa, ca, sb, cb, sc, cc;
        __sincosf(d.x, &sa, &ca);
        __sincosf(d.y, &sb, &cb);
        __sincosf(d.w, &sc, &cc);
        float x = d.z;
        H.m[0] = cb;      H.m[1]  = -sb * cc;             H.m[2]  = sb * sc;               H.m[3]  = cb * x;
        H.m[4] = ca * sb; H.m[5]  = ca * cb * cc - sa*sc; H.m[6]  = -ca * cb * sc - sa*cc; H.m[7]  = ca * sb * x;
        H.m[8] = sa * sb; H.m[9]  = sa * cb * cc + ca*sc; H.m[10] = -sa * cb * sc + ca*cc; H.m[11] = sa * sb * x;
    } else {
        float a = d.w;
        float b = full_dofs[n * 9 + 4];
        float g = full_dofs[n * 9 + 5];
        float sa, ca, sb, cb, sg, cg;
        __sincosf(a, &sa, &ca);
        __sincosf(b, &sb, &cb);
        __sincosf(g, &sg, &cg);
        H.m[0] = cg * cb; H.m[1]  = cg * sb * sa - sg * ca; H.m[2]  = cg * sb * ca + sg * sa; H.m[3]  = d.x;
        H.m[4] = sg * cb; H.m[5]  = sg * sb * sa + cg * ca; H.m[6]  = sg * sb * ca - cg * sa; H.m[7]  = d.y;
        H.m[8] = -sb;     H.m[9]  = cb * sa;                H.m[10] = cb * ca;                H.m[11] = d.z;
    }
    return H;
}

// ---------------- fused kernel: backbone scan + side chains ------------------
__global__ void __launch_bounds__(NT)
k_fused(const float4* __restrict__ dofs4,
        const float* __restrict__ full_dofs,
        const int* __restrict__ doftype,
        const int* __restrict__ kin_id,
        float* __restrict__ out) {
    const int t    = threadIdx.x;
    const int bid  = blockIdx.x;
    const int item = bid * NT + t;
    const int n    = item + 1;        // backbone node id
    const int lane = t & 31;
    const int warp = t >> 5;

    // ---- prefetch this thread's side chain (overlaps the backbone scan) ----
    const int nb = 1 + B_CHAIN + item * S_SIDE;  // first side node
    float4 sd[S_SIDE];
    int    sdt[S_SIDE];
    int    sid[S_SIDE];
#pragma unroll
    for (int d = 0; d < S_SIDE; ++d) {
        sd[d]  = dofs4[nb + d - 1];
        sdt[d] = doftype[nb + d];
        sid[d] = kin_id[nb + d];
    }
    const int bb_out = kin_id[n];

    // ---- backbone: build + warp shuffle scan ----
    Aff M = build_ht_from(doftype[n], dofs4[n - 1], n, full_dofs);

#pragma unroll
    for (int d = 1; d < 32; d <<= 1) {
        Aff P = shfl_up_aff(M, d);
        if (lane >= d) M = aff_mul(P, M);
    }

    // cross-warp fixup
    __shared__ float wagg[4][12];
    __shared__ float wred[4][12];
    if (lane == 31) {
#pragma unroll
        for (int k = 0; k < 12; ++k) wagg[warp][k] = M.m[k];
    }
    __syncthreads();
    {
        Aff Wp = aff_identity();
        for (int w = 0; w < warp; ++w) {
            Aff A;
#pragma unroll
            for (int k = 0; k < 12; ++k) A.m[k] = wagg[w][k];
            Wp = aff_mul(Wp, A);
        }
        M = aff_mul(Wp, M);   // block-local inclusive value
    }

    // publish block aggregate (thread NT-1 holds it)
    if (t == NT - 1) {
#pragma unroll
        for (int k = 0; k < 12; ++k) g_agg[bid * 12 + k] = M.m[k];
        __threadfence();
        atomicExch(&g_flag[bid], 1);
    }

    // lookback: thread i covers predecessor block i (identity for i >= bid)
    Aff V = aff_identity();
    if (t < bid) {
        volatile int* vf = (volatile int*)g_flag;
        while (vf[t] == 0) { }
        __threadfence();
#pragma unroll
        for (int k = 0; k < 12; ++k) V.m[k] = __ldcg(&g_agg[t * 12 + k]);
    }
    // ordered tree reduce (order preserved: low index = left operand)
#pragma unroll
    for (int d = 1; d < 32; d <<= 1) {
        Aff H = shfl_down_aff(V, d);
        if ((lane & (2 * d - 1)) == 0) V = aff_mul(V, H);
    }
    if (lane == 0) {
#pragma unroll
        for (int k = 0; k < 12; ++k) wred[warp][k] = V.m[k];
    }
    __syncthreads();
    {
        Aff w0, w1, w2, w3;
#pragma unroll
        for (int k = 0; k < 12; ++k) { w0.m[k] = wred[0][k]; w1.m[k] = wred[1][k];
                                       w2.m[k] = wred[2][k]; w3.m[k] = wred[3][k]; }
        Aff E = aff_mul(aff_mul(w0, w1), aff_mul(w2, w3));  // exclusive block prefix
        M = aff_mul(E, M);                                  // global transform of node n
    }

    // reset flags for the next graph replay: the last block to finish the
    // lookback (all its threads are past the spin, per the __syncthreads above)
    // clears the scratch. All lookback reads chip-wide happen-before this.
    if (t == 0) {
        int c = atomicAdd(&g_done, 1);
        if (c == NB - 1) {
            for (int i = 0; i < NB; ++i) g_flag[i] = 0;
            g_done = 0;
        }
    }

    // backbone coordinate
    out[bb_out * 3 + 0] = M.m[3];
    out[bb_out * 3 + 1] = M.m[7];
    out[bb_out * 3 + 2] = M.m[11];

    // ---- side chain: serial walk, builds are independent (full ILP) ----
#pragma unroll
    for (int d = 0; d < S_SIDE; ++d) {
        Aff H = build_ht_from(sdt[d], sd[d], nb + d, full_dofs);
        M = aff_mul(M, H);
        int o = sid[d];
        out[o * 3 + 0] = M.m[3];
        out[o * 3 + 1] = M.m[7];
        out[o * 3 + 2] = M.m[11];
    }
}

// ---------------- launch -----------------------------------------------------
extern "C" void kernel_launch(void* const* d_in, const int* in_sizes, int n_in,
                              void* d_out, int out_size) {
    // metadata order: dofs, full_dofs, node_idx, dof_idx, doftype,
    //                 gen0_nodes, gen1_nodes, gen1_parents, kin_id
    const float4* dofs4     = (const float4*)d_in[0];
    const float*  full_dofs = (const float*)d_in[1];
    const int*    doftype   = (const int*)d_in[4];
    const int*    kin_id    = (const int*)d_in[8];
    float* out = (float*)d_out;

    k_fused<<<NB, NT>>>(dofs4, full_dofs, doftype, kin_id, out);
}